// round 2
// baseline (speedup 1.0000x reference)
#include <cuda_runtime.h>
#include <cuda_bf16.h>
#include <math.h>

// Problem constants
#define B_DIM 8
#define C_DIM 256
#define S_DIM 8192            // D*H*W = 8*32*32
#define N_PTS 65536           // B*S
#define N_CODES 1024
#define Z_ELEMS 16777216      // B*C*S
#define BATCH_STRIDE 2097152  // C*S

// Output layout (concatenated, fp32)
#define ZQ_OFF 0
#define IDX_OFF 16777216
#define LOSS_OFF 16842752
#define PERP_OFF 16842753

// Tiles for scoring kernel
#define M_TILE 64
#define N_CHUNK 64
#define SMEM_B_BYTES (2 * 256 * 64 * 4)   // Zs + Es = 128 KB

// Scratch (device globals; no allocation allowed)
__device__ float  g_e2[N_CODES];     // ||e_j||^2 (fp32, matches ref's B_j scale)
__device__ int    g_idx[N_PTS];      // argmin index per point
__device__ float  g_cnt[N_CODES];    // histogram
__device__ double g_loss;            // sum of squared commitment diffs

// ---------------------------------------------------------------------------
// Kernel A: per-code ||e||^2, zero scratch accumulators.
// ---------------------------------------------------------------------------
__global__ void vq_prep_kernel(const float* __restrict__ embed) {
    int t = threadIdx.x;
    int lane = t & 31;
    int code = blockIdx.x * 8 + (t >> 5);
    const float* row = embed + code * C_DIM;
    float s = 0.f;
#pragma unroll
    for (int q = 0; q < 8; ++q) {
        float e = row[lane + q * 32];
        s = fmaf(e, e, s);
    }
#pragma unroll
    for (int off = 16; off > 0; off >>= 1)
        s += __shfl_down_sync(0xffffffffu, s, off);
    if (lane == 0) g_e2[code] = s;

    if (blockIdx.x == 0) {
        for (int i = t; i < N_CODES; i += 256) g_cnt[i] = 0.f;
        if (t == 0) g_loss = 0.0;
    }
}

// ---------------------------------------------------------------------------
// Kernel B: fused scoring GEMM + quantized-distance argmin.
// Replicates reference rounding: dist = fl32(fl32(A + Bj) - 2*Mj),
// argmin with lowest-index tie-break (lexicographic compare).
// grid 1024 blocks (64 points each), 256 threads as 16x16, 4x4 microtiles.
// ---------------------------------------------------------------------------
__global__ void vq_argmin_kernel(const float* __restrict__ z,
                                 const float* __restrict__ embed,
                                 float* __restrict__ out) {
    extern __shared__ float smem[];
    float* Zs = smem;                 // [k*64 + m]
    float* Es = smem + 256 * 64;      // [k*64 + j]
    __shared__ float sA[M_TILE];      // per-point ||z||^2 (fp32)

    const int t  = threadIdx.x;
    const int tx = t & 15;
    const int ty = t >> 4;
    const int tb = blockIdx.x;

    const int b  = tb >> 7;                 // 128 tiles per batch
    const int s0 = (tb & 127) * M_TILE;
    const float* zb = z + (size_t)b * BATCH_STRIDE + s0;

    // Load Z tile: coalesced float4 along spatial dim.
#pragma unroll
    for (int i = 0; i < 16; ++i) {
        int lin = i * 256 + t;
        int k   = lin >> 4;
        int mq  = lin & 15;
        float4 v = *(const float4*)(zb + (size_t)k * S_DIM + mq * 4);
        *(float4*)(Zs + k * 64 + mq * 4) = v;
    }
    __syncthreads();

    // Per-point A = sum(z^2) in fp32 (value only matters modulo ulp-grid
    // shifts of the ~256-magnitude dist, so plain sequential fp32 is exact
    // enough — see binade-shift invariance).
    if (t < M_TILE) {
        float a = 0.f;
#pragma unroll 8
        for (int k = 0; k < 256; ++k) {
            float v = Zs[k * 64 + t];
            a = fmaf(v, v, a);
        }
        sA[t] = a;
    }

    float bestd[4];
    int   bidx[4];
#pragma unroll
    for (int p = 0; p < 4; ++p) { bestd[p] = INFINITY; bidx[p] = N_CODES; }

    for (int ch = 0; ch < N_CODES / N_CHUNK; ++ch) {
        if (ch) __syncthreads();
        const int jb = ch * N_CHUNK;
#pragma unroll
        for (int i = 0; i < 16; ++i) {
            int lin  = i * 256 + t;
            int code = lin & 63;
            int kq   = lin >> 6;
            float4 v = *(const float4*)(embed + (size_t)(jb + code) * C_DIM + kq * 4);
            Es[(kq * 4 + 0) * 64 + code] = v.x;
            Es[(kq * 4 + 1) * 64 + code] = v.y;
            Es[(kq * 4 + 2) * 64 + code] = v.z;
            Es[(kq * 4 + 3) * 64 + code] = v.w;
        }
        __syncthreads();

        float acc[4][4];
#pragma unroll
        for (int p = 0; p < 4; ++p)
#pragma unroll
            for (int q = 0; q < 4; ++q) acc[p][q] = 0.f;

        const float* zp = Zs + (tx << 2);
        const float* ep = Es + (ty << 2);
#pragma unroll 4
        for (int k = 0; k < 256; ++k) {
            float4 a = *(const float4*)(zp + k * 64);
            float4 e = *(const float4*)(ep + k * 64);
            acc[0][0] = fmaf(a.x, e.x, acc[0][0]);
            acc[0][1] = fmaf(a.x, e.y, acc[0][1]);
            acc[0][2] = fmaf(a.x, e.z, acc[0][2]);
            acc[0][3] = fmaf(a.x, e.w, acc[0][3]);
            acc[1][0] = fmaf(a.y, e.x, acc[1][0]);
            acc[1][1] = fmaf(a.y, e.y, acc[1][1]);
            acc[1][2] = fmaf(a.y, e.z, acc[1][2]);
            acc[1][3] = fmaf(a.y, e.w, acc[1][3]);
            acc[2][0] = fmaf(a.z, e.x, acc[2][0]);
            acc[2][1] = fmaf(a.z, e.y, acc[2][1]);
            acc[2][2] = fmaf(a.z, e.z, acc[2][2]);
            acc[2][3] = fmaf(a.z, e.w, acc[2][3]);
            acc[3][0] = fmaf(a.w, e.x, acc[3][0]);
            acc[3][1] = fmaf(a.w, e.y, acc[3][1]);
            acc[3][2] = fmaf(a.w, e.z, acc[3][2]);
            acc[3][3] = fmaf(a.w, e.w, acc[3][3]);
        }

        // Reference-rounded distance: t1 = fl(A + Bj); d = fl(t1 - 2*Mj).
        // (2*acc is exact; the subtract gives the same single rounding as ref.)
        // Ascending j traversal -> strict '<' reproduces lowest-index ties.
#pragma unroll
        for (int q = 0; q < 4; ++q) {
            int j = jb + (ty << 2) + q;
            float Bj = g_e2[j];
#pragma unroll
            for (int p = 0; p < 4; ++p) {
                float t1 = __fadd_rn(sA[(tx << 2) + p], Bj);
                float d  = __fadd_rn(t1, -2.0f * acc[p][q]);
                if (d < bestd[p]) { bestd[p] = d; bidx[p] = j; }
            }
        }
    }

    // Cross-thread reduction: MUST be lexicographic (dist, index) because
    // quantized dist ties are common and ty order != index order here.
    __syncthreads();
    float* sS = Es;
    int*   sI = (int*)(Es + 1024);
#pragma unroll
    for (int p = 0; p < 4; ++p) {
        int m = (tx << 2) + p;
        sS[m * 16 + ty] = bestd[p];
        sI[m * 16 + ty] = bidx[p];
    }
    __syncthreads();
    if (t < M_TILE) {
        float bd = INFINITY; int bi = N_CODES;
#pragma unroll
        for (int y = 0; y < 16; ++y) {
            float v = sS[t * 16 + y];
            int   i = sI[t * 16 + y];
            if (v < bd || (v == bd && i < bi)) { bd = v; bi = i; }
        }
        int n = tb * M_TILE + t;
        g_idx[n] = bi;
        out[IDX_OFF + n] = (float)bi;
    }
}

// ---------------------------------------------------------------------------
// Kernel C: z_q = fl(z + fl(embed[idx] - z))  (STE rounding emulation),
// commitment loss partials, histogram.
// ---------------------------------------------------------------------------
__global__ void vq_quantize_kernel(const float* __restrict__ z,
                                   const float* __restrict__ embed,
                                   float* __restrict__ out) {
    __shared__ int    sidx[M_TILE];
    __shared__ double red[256];

    const int t  = threadIdx.x;
    const int tb = blockIdx.x;
    const int b  = tb >> 7;
    const int s0 = (tb & 127) * M_TILE;

    if (t < M_TILE) {
        int id = g_idx[tb * M_TILE + t];
        sidx[t] = id;
        atomicAdd(&g_cnt[id], 1.0f);
    }
    __syncthreads();

    const float* zb = z   + (size_t)b * BATCH_STRIDE + s0;
    float*       qb = out + ZQ_OFF + (size_t)b * BATCH_STRIDE + s0;

    double lacc = 0.0;
#pragma unroll
    for (int i = 0; i < 16; ++i) {
        int lin = i * 256 + t;
        int c   = lin >> 4;
        int mq  = lin & 15;
        float4 zv = *(const float4*)(zb + (size_t)c * S_DIM + mq * 4);
        float4 ev;
        ev.x = __ldg(embed + (size_t)sidx[mq * 4 + 0] * C_DIM + c);
        ev.y = __ldg(embed + (size_t)sidx[mq * 4 + 1] * C_DIM + c);
        ev.z = __ldg(embed + (size_t)sidx[mq * 4 + 2] * C_DIM + c);
        ev.w = __ldg(embed + (size_t)sidx[mq * 4 + 3] * C_DIM + c);
        // diffs (also the commitment residuals, pre-STE)
        float dx = __fadd_rn(ev.x, -zv.x);
        float dy = __fadd_rn(ev.y, -zv.y);
        float dz = __fadd_rn(ev.z, -zv.z);
        float dw = __fadd_rn(ev.w, -zv.w);
        float4 qv;
        qv.x = __fadd_rn(zv.x, dx);
        qv.y = __fadd_rn(zv.y, dy);
        qv.z = __fadd_rn(zv.z, dz);
        qv.w = __fadd_rn(zv.w, dw);
        *(float4*)(qb + (size_t)c * S_DIM + mq * 4) = qv;
        lacc += (double)(dx * dx) + (double)(dy * dy)
              + (double)(dz * dz) + (double)(dw * dw);
    }

    red[t] = lacc;
    __syncthreads();
    for (int off = 128; off > 0; off >>= 1) {
        if (t < off) red[t] += red[t + off];
        __syncthreads();
    }
    if (t == 0) atomicAdd(&g_loss, red[0]);
}

// ---------------------------------------------------------------------------
// Kernel D: finalize loss + perplexity.
// ---------------------------------------------------------------------------
__global__ void vq_finalize_kernel(float* __restrict__ out) {
    __shared__ float sred[1024];
    int t = threadIdx.x;
    float cnt = g_cnt[t];
    float p = cnt * (1.0f / (float)N_PTS);
    sred[t] = p * logf(p + 1e-10f);
    __syncthreads();
    for (int off = 512; off > 0; off >>= 1) {
        if (t < off) sred[t] += sred[t + off];
        __syncthreads();
    }
    if (t == 0) {
        out[PERP_OFF] = expf(-sred[0]);
        out[LOSS_OFF] = 0.25f * (float)(g_loss / (double)Z_ELEMS);
    }
}

// ---------------------------------------------------------------------------
extern "C" void kernel_launch(void* const* d_in, const int* in_sizes, int n_in,
                              void* d_out, int out_size) {
    const float* z     = (const float*)d_in[0];
    const float* embed = (const float*)d_in[1];
    float* out = (float*)d_out;

    cudaFuncSetAttribute(vq_argmin_kernel,
                         cudaFuncAttributeMaxDynamicSharedMemorySize,
                         SMEM_B_BYTES);

    vq_prep_kernel<<<128, 256>>>(embed);
    vq_argmin_kernel<<<N_PTS / M_TILE, 256, SMEM_B_BYTES>>>(z, embed, out);
    vq_quantize_kernel<<<N_PTS / M_TILE, 256>>>(z, embed, out);
    vq_finalize_kernel<<<1, 1024>>>(out);
}

// round 4
// speedup vs baseline: 1.6372x; 1.6372x over previous
#include <cuda_runtime.h>
#include <cuda_bf16.h>
#include <cstdint>
#include <math.h>

// Problem constants
#define B_DIM 8
#define C_DIM 256
#define S_DIM 8192            // D*H*W
#define N_PTS 65536           // B*S
#define N_CODES 1024
#define Z_ELEMS 16777216
#define BATCH_STRIDE 2097152  // C*S

// Output layout (concatenated, fp32)
#define ZQ_OFF 0
#define IDX_OFF 16777216
#define LOSS_OFF 16842752
#define PERP_OFF 16842753

// Scoring-kernel tiling: 128 points x 512 codes per block, K split in 64-subchunks
#define MT 128                 // points per block
#define NC_HALF 512            // codes per block (grid.y = 2)
#define NCHUNK 128             // codes per accumulation chunk
#define KSUB 64                // K sub-chunk (cp.async double buffered)
#define SMEM_ARGMIN (256*128*4 + 2*128*64*4)   // Zs 128KB + 2 Es bufs 32KB = 192KB

typedef unsigned long long ull;

// Scratch
__device__ float g_e2[N_CODES];        // ||e_j||^2
__device__ float g_bd[2][N_PTS];       // per-half best dist
__device__ int   g_bi[2][N_PTS];       // per-half best index
__device__ float g_cnt[N_CODES];
__device__ double g_loss;

// ---- f32x2 helpers (packed dual-fp32; lanes are plain IEEE fp32 FMAs) ----
__device__ __forceinline__ ull pack2(float lo, float hi) {
    ull r; asm("mov.b64 %0, {%1, %2};" : "=l"(r) : "f"(lo), "f"(hi)); return r;
}
__device__ __forceinline__ void unpack2(ull v, float& lo, float& hi) {
    asm("mov.b64 {%0, %1}, %2;" : "=f"(lo), "=f"(hi) : "l"(v));
}
__device__ __forceinline__ ull fma2(ull a, ull b, ull c) {
    ull d; asm("fma.rn.f32x2 %0, %1, %2, %3;" : "=l"(d) : "l"(a), "l"(b), "l"(c)); return d;
}
__device__ __forceinline__ void cp16(unsigned saddr, const void* g) {
    asm volatile("cp.async.cg.shared.global [%0], [%1], 16;" :: "r"(saddr), "l"(g));
}
#define CP_COMMIT() asm volatile("cp.async.commit_group;")
#define CP_WAIT1()  asm volatile("cp.async.wait_group 1;")
#define CP_WAIT0()  asm volatile("cp.async.wait_group 0;")

// ---------------------------------------------------------------------------
// Kernel A: ||e_j||^2 + zero accumulators.
// ---------------------------------------------------------------------------
__global__ void vq_prep_kernel(const float* __restrict__ embed) {
    int t = threadIdx.x, lane = t & 31;
    int code = blockIdx.x * 8 + (t >> 5);
    const float* row = embed + code * C_DIM;
    float s = 0.f;
#pragma unroll
    for (int q = 0; q < 8; ++q) { float e = row[lane + q * 32]; s = fmaf(e, e, s); }
#pragma unroll
    for (int off = 16; off > 0; off >>= 1) s += __shfl_down_sync(0xffffffffu, s, off);
    if (lane == 0) g_e2[code] = s;
    if (blockIdx.x == 0) {
        for (int i = t; i < N_CODES; i += 256) g_cnt[i] = 0.f;
        if (t == 0) g_loss = 0.0;
    }
}

// ---------------------------------------------------------------------------
// Kernel B: scoring GEMM (f32x2) + quantized-distance argmin.
// grid (512, 2): x = 128-point tile, y = 512-code half.
// 256 threads as 16x16, each an 8(points) x 8(codes) microtile.
// Accumulators packed along points -> A pairs come free via LDS.64.
// ---------------------------------------------------------------------------
__global__ void __launch_bounds__(256, 1)
vq_argmin_kernel(const float* __restrict__ z, const float* __restrict__ embed) {
    extern __shared__ float smem[];
    float* Zs  = smem;                    // [k 0..255][m 0..127]
    float* Eb[2] = { smem + 256 * 128, smem + 256 * 128 + 128 * 64 }; // [j 0..127][k 0..63]
    __shared__ float sA[MT];

    const int t  = threadIdx.x;
    const int tx = t & 15;
    const int ty = t >> 4;
    const int tileM = blockIdx.x;         // 0..511
    const int cy    = blockIdx.y;         // 0..1
    const int cbase = cy * NC_HALF;

    const int b  = tileM >> 6;            // 64 tiles per batch
    const int s0 = (tileM & 63) * MT;
    const float* zb = z + (size_t)b * BATCH_STRIDE + s0;

    // Load Z tile [256 k][128 m], coalesced float4 along m.
#pragma unroll
    for (int i = 0; i < 32; ++i) {
        int lin = i * 256 + t;
        int k = lin >> 5, mq = lin & 31;
        *(float4*)(Zs + k * 128 + mq * 4) = *(const float4*)(zb + (size_t)k * S_DIM + mq * 4);
    }

    // Prefetch E sub-chunk 0 into Eb[0]. Each sub = 128 codes x 64 k = 32KB.
    {
        unsigned sb = (unsigned)__cvta_generic_to_shared(Eb[0]);
#pragma unroll
        for (int i = 0; i < 8; ++i) {
            int lin = i * 256 + t;
            int code = lin >> 4, seg = lin & 15;
            cp16(sb + (unsigned)(code * 64 + seg * 4) * 4,
                 embed + (size_t)(cbase + code) * C_DIM + seg * 4);
        }
        CP_COMMIT();
    }
    __syncthreads();

    // Per-point A = sum(z^2), fp32 sequential (argmin-invariant modulo grid shift).
    if (t < MT) {
        float a = 0.f;
#pragma unroll 8
        for (int k = 0; k < 256; ++k) { float v = Zs[k * 128 + t]; a = fmaf(v, v, a); }
        sA[t] = a;
    }

    ull acc[4][8];
#pragma unroll
    for (int pp = 0; pp < 4; ++pp)
#pragma unroll
        for (int q = 0; q < 8; ++q) acc[pp][q] = 0ull;

    float bestd[8]; int bidx[8];
#pragma unroll
    for (int p = 0; p < 8; ++p) { bestd[p] = INFINITY; bidx[p] = N_CODES; }

    // 16 sub-chunks: chunk = s>>2 (128 codes), k-quarter = s&3.
    for (int s = 0; s < 16; ++s) {
        if (s < 15) {  // prefetch next sub into the other buffer
            int ns = s + 1;
            int jb = cbase + (ns >> 2) * NCHUNK;
            int k0 = (ns & 3) * KSUB;
            unsigned sb = (unsigned)__cvta_generic_to_shared(Eb[ns & 1]);
#pragma unroll
            for (int i = 0; i < 8; ++i) {
                int lin = i * 256 + t;
                int code = lin >> 4, seg = lin & 15;
                cp16(sb + (unsigned)(code * 64 + seg * 4) * 4,
                     embed + (size_t)(jb + code) * C_DIM + k0 + seg * 4);
            }
            CP_COMMIT();
            CP_WAIT1();
        } else {
            CP_WAIT0();
        }
        __syncthreads();

        const float* E  = Eb[s & 1];
        const float* Er = E + (ty * 8) * 64;    // this thread's 8 code rows
        const int kb = (s & 3) * KSUB;

        for (int k4 = 0; k4 < KSUB; k4 += 4) {
            float e4[8][4];
#pragma unroll
            for (int q = 0; q < 8; ++q)
                *(float4*)e4[q] = *(const float4*)(Er + q * 64 + k4);
#pragma unroll
            for (int kk = 0; kk < 4; ++kk) {
                const ull* ap = (const ull*)(Zs + (kb + k4 + kk) * 128 + tx * 8);
                ull a0 = ap[0], a1 = ap[1], a2 = ap[2], a3 = ap[3];
#pragma unroll
                for (int q = 0; q < 8; ++q) {
                    ull eb = pack2(e4[q][kk], e4[q][kk]);
                    acc[0][q] = fma2(a0, eb, acc[0][q]);
                    acc[1][q] = fma2(a1, eb, acc[1][q]);
                    acc[2][q] = fma2(a2, eb, acc[2][q]);
                    acc[3][q] = fma2(a3, eb, acc[3][q]);
                }
            }
        }

        if ((s & 3) == 3) {
            // Chunk complete: reference-rounded dist + running argmin.
            // Ascending j within thread -> strict '<' keeps lowest index.
            int jb = cbase + (s >> 2) * NCHUNK;
#pragma unroll
            for (int q = 0; q < 8; ++q) {
                int j = jb + ty * 8 + q;
                float Bj = __ldg(&g_e2[j]);
#pragma unroll
                for (int pp = 0; pp < 4; ++pp) {
                    float m0, m1; unpack2(acc[pp][q], m0, m1);
                    float t0 = __fadd_rn(sA[tx * 8 + 2 * pp],     Bj);
                    float t1 = __fadd_rn(sA[tx * 8 + 2 * pp + 1], Bj);
                    float d0 = __fadd_rn(t0, -2.0f * m0);
                    float d1 = __fadd_rn(t1, -2.0f * m1);
                    if (d0 < bestd[2 * pp])     { bestd[2 * pp] = d0;     bidx[2 * pp] = j; }
                    if (d1 < bestd[2 * pp + 1]) { bestd[2 * pp + 1] = d1; bidx[2 * pp + 1] = j; }
                    acc[pp][q] = 0ull;
                }
            }
        }
        __syncthreads();
    }

    // Cross-thread (ty) lexicographic argmin per point. Reuse Eb[0] space.
    float* sS = Eb[0];                 // [128][16]
    int*   sI = (int*)(Eb[0] + MT * 16);
#pragma unroll
    for (int p = 0; p < 8; ++p) {
        int m = tx * 8 + p;
        sS[m * 16 + ty] = bestd[p];
        sI[m * 16 + ty] = bidx[p];
    }
    __syncthreads();
    if (t < MT) {
        float bd = INFINITY; int bi = N_CODES;
#pragma unroll
        for (int y = 0; y < 16; ++y) {
            float v = sS[t * 16 + y];
            int   i = sI[t * 16 + y];
            if (v < bd || (v == bd && i < bi)) { bd = v; bi = i; }
        }
        int n = tileM * MT + t;        // == b*8192 + s0 + t
        g_bd[cy][n] = bd;
        g_bi[cy][n] = bi;
    }
}

// ---------------------------------------------------------------------------
// Kernel C: merge halves -> idx; z_q = fl(z + fl(e - z)); loss; histogram.
// grid 1024 x 256; 64 points per block.
// ---------------------------------------------------------------------------
__global__ void vq_quantize_kernel(const float* __restrict__ z,
                                   const float* __restrict__ embed,
                                   float* __restrict__ out) {
    __shared__ int    sidx[64];
    __shared__ double red[256];

    const int t  = threadIdx.x;
    const int tb = blockIdx.x;
    const int b  = tb >> 7;
    const int s0 = (tb & 127) * 64;

    if (t < 64) {
        int n = tb * 64 + t;
        float d0 = g_bd[0][n], d1 = g_bd[1][n];
        // half 0 holds all lower code indices -> tie goes to half 0.
        int id = (d1 < d0) ? g_bi[1][n] : g_bi[0][n];
        sidx[t] = id;
        out[IDX_OFF + n] = (float)id;
        atomicAdd(&g_cnt[id], 1.0f);
    }
    __syncthreads();

    const float* zb = z   + (size_t)b * BATCH_STRIDE + s0;
    float*       qb = out + ZQ_OFF + (size_t)b * BATCH_STRIDE + s0;

    double lacc = 0.0;
#pragma unroll
    for (int i = 0; i < 16; ++i) {
        int lin = i * 256 + t;
        int c = lin >> 4, mq = lin & 15;
        float4 zv = *(const float4*)(zb + (size_t)c * S_DIM + mq * 4);
        float4 ev;
        ev.x = __ldg(embed + (size_t)sidx[mq * 4 + 0] * C_DIM + c);
        ev.y = __ldg(embed + (size_t)sidx[mq * 4 + 1] * C_DIM + c);
        ev.z = __ldg(embed + (size_t)sidx[mq * 4 + 2] * C_DIM + c);
        ev.w = __ldg(embed + (size_t)sidx[mq * 4 + 3] * C_DIM + c);
        float dx = __fadd_rn(ev.x, -zv.x);
        float dy = __fadd_rn(ev.y, -zv.y);
        float dz = __fadd_rn(ev.z, -zv.z);
        float dw = __fadd_rn(ev.w, -zv.w);
        float4 qv;
        qv.x = __fadd_rn(zv.x, dx);
        qv.y = __fadd_rn(zv.y, dy);
        qv.z = __fadd_rn(zv.z, dz);
        qv.w = __fadd_rn(zv.w, dw);
        *(float4*)(qb + (size_t)c * S_DIM + mq * 4) = qv;
        lacc += (double)(dx * dx) + (double)(dy * dy)
              + (double)(dz * dz) + (double)(dw * dw);
    }

    red[t] = lacc;
    __syncthreads();
    for (int off = 128; off > 0; off >>= 1) {
        if (t < off) red[t] += red[t + off];
        __syncthreads();
    }
    if (t == 0) atomicAdd(&g_loss, red[0]);
}

// ---------------------------------------------------------------------------
// Kernel D: finalize loss + perplexity.
// ---------------------------------------------------------------------------
__global__ void vq_finalize_kernel(float* __restrict__ out) {
    __shared__ float sred[1024];
    int t = threadIdx.x;
    float p = g_cnt[t] * (1.0f / (float)N_PTS);
    sred[t] = p * logf(p + 1e-10f);
    __syncthreads();
    for (int off = 512; off > 0; off >>= 1) {
        if (t < off) sred[t] += sred[t + off];
        __syncthreads();
    }
    if (t == 0) {
        out[PERP_OFF] = expf(-sred[0]);
        out[LOSS_OFF] = 0.25f * (float)(g_loss / (double)Z_ELEMS);
    }
}

// ---------------------------------------------------------------------------
extern "C" void kernel_launch(void* const* d_in, const int* in_sizes, int n_in,
                              void* d_out, int out_size) {
    const float* z     = (const float*)d_in[0];
    const float* embed = (const float*)d_in[1];
    float* out = (float*)d_out;

    cudaFuncSetAttribute(vq_argmin_kernel,
                         cudaFuncAttributeMaxDynamicSharedMemorySize,
                         SMEM_ARGMIN);

    vq_prep_kernel<<<128, 256>>>(embed);
    dim3 grid(N_PTS / MT, 2);
    vq_argmin_kernel<<<grid, 256, SMEM_ARGMIN>>>(z, embed);
    vq_quantize_kernel<<<1024, 256>>>(z, embed, out);
    vq_finalize_kernel<<<1, 1024>>>(out);
}